// round 13
// baseline (speedup 1.0000x reference)
#include <cuda_runtime.h>
#include <cuda_bf16.h>
#include <cstdint>

// Problem constants (fixed shapes)
#define B_SZ   256
#define T_SZ   512
#define EMB    128
#define HID    256
#define NCLS   32000

// Device scratch: h0 (bf16) and W converted to bf16 (recomputed every run)
__device__ __nv_bfloat16 g_h0[B_SZ * HID];
__device__ __nv_bfloat16 g_Wbf[NCLS * HID];   // 16.4 MB

// ---------------------------------------------------------------------------
// Kernel 1 (prep): blocks 0..127 = LSTM h0 (validated math);
//                  blocks 128..383 = W fp32 -> bf16 conversion.
// ---------------------------------------------------------------------------
__global__ void __launch_bounds__(256) prep_kernel(
    const int* __restrict__ X, const float* __restrict__ C_table,
    const float* __restrict__ U_i, const float* __restrict__ b_i,
    const float* __restrict__ U_c, const float* __restrict__ b_c,
    const float* __restrict__ U_o, const float* __restrict__ b_o,
    const float* __restrict__ W_w)
{
    const int tid = threadIdx.x;
    const int bid = blockIdx.x;

    if (bid >= 128) {
        // ---- W conversion: 2,048,000 float4 -> uint2 (4 bf16) each ----
        const float4* src = (const float4*)W_w;
        const int total4 = (NCLS * HID) / 4;          // 2,048,000
        for (int i = (bid - 128) * 256 + tid; i < total4; i += 256 * 256) {
            float4 v = src[i];
            __nv_bfloat162 p0 = __floats2bfloat162_rn(v.x, v.y);
            __nv_bfloat162 p1 = __floats2bfloat162_rn(v.z, v.w);
            uint2 u;
            u.x = *(uint32_t*)&p0;
            u.y = *(uint32_t*)&p1;
            *(uint2*)(g_Wbf + (size_t)i * 4) = u;
        }
        return;
    }

    // ---- LSTM h0 (validated; bx = hidden split, by = batch group) ----
    __shared__ float E_s[8][EMB];
    const int bx = bid & 3;
    const int by = bid >> 2;
    const int b0 = by * 8;

    for (int i = tid; i < 8 * EMB; i += 256) {
        int b = i >> 7;
        int e = i & (EMB - 1);
        int tok = X[(b0 + b) * T_SZ + (T_SZ - 1)];
        E_s[b][e] = C_table[tok * EMB + e];
    }
    __syncthreads();

    const int h    = bx * 64 + (tid & 63);
    const int bsub = tid >> 6;
    const int r0   = bsub * 2;

    float ai[2], ag[2], ao[2];
    const float bi = b_i[h], bc = b_c[h], bo = b_o[h];
#pragma unroll
    for (int r = 0; r < 2; r++) { ai[r] = bi; ag[r] = bc; ao[r] = bo; }

#pragma unroll 4
    for (int e = 0; e < EMB; e++) {
        float ui = U_i[e * HID + h];
        float uc = U_c[e * HID + h];
        float uo = U_o[e * HID + h];
#pragma unroll
        for (int r = 0; r < 2; r++) {
            float ev = E_s[r0 + r][e];
            ai[r] = fmaf(ev, ui, ai[r]);
            ag[r] = fmaf(ev, uc, ag[r]);
            ao[r] = fmaf(ev, uo, ao[r]);
        }
    }

#pragma unroll
    for (int r = 0; r < 2; r++) {
        float i0 = 1.0f / (1.0f + __expf(-ai[r]));
        float g0 = tanhf(ag[r]);
        float o0 = 1.0f / (1.0f + __expf(-ao[r]));
        float c0 = i0 * g0;
        float h0 = o0 * tanhf(c0);
        g_h0[(b0 + r0 + r) * HID + h] = __float2bfloat16(h0);
    }
}

// ---------------------------------------------------------------------------
// Kernel 2: logits[256, 32000] = h0 @ Wbf^T + b_out
// Balanced persistent bf16 mma.sync GEMM; B is bf16 end-to-end:
// cp.async bf16 chunks -> smem (stride 40 bf16 = 80B) -> ldmatrix.x4 B
// fragments (R5-validated lane mapping) -> mma. No consumer CVTs.
//   GRID = 125 CTAs x 512 thr; 2 tiles per CTA (bid, bid+125); 16 phases;
//   CHUNK_K=32 bf16; 4 buffers; wait_group 2; issue-before-compute;
//   per-wn-group named barriers (R12).
// ---------------------------------------------------------------------------
#define BM      256
#define BN      128
#define ASTR    264              // A_s row stride in bf16 (528B = 33*16)
#define CHUNK_K 32
#define NCHUNK  8                // chunks per tile
#define NPHASE  16               // 2 tiles x 8 chunks
#define NBUF    4
#define BSTRB   40               // B_s row stride in bf16 (80B; (5r)%8 banks)
#define BBUFB   (BN * BSTRB)     // one B buffer, bf16 elems (5120)
#define GRID2   125
#define NTILES  (NCLS / BN)      // 250

__device__ __forceinline__ void cp16(void* dst_smem, const void* src) {
    uint32_t d = (uint32_t)__cvta_generic_to_shared(dst_smem);
    asm volatile("cp.async.cg.shared.global [%0], [%1], 16;" :: "r"(d), "l"(src));
}
__device__ __forceinline__ void cp_commit() {
    asm volatile("cp.async.commit_group;" ::: "memory");
}
__device__ __forceinline__ void cp_wait2() {
    asm volatile("cp.async.wait_group 2;" ::: "memory");
}
__device__ __forceinline__ void group_bar(int wn) {
    asm volatile("bar.sync %0, 128;" :: "r"(1 + wn) : "memory");
}

// Issue this wn-group's 32 rows of one bf16 B chunk: 128 segs of 16B,
// exactly ONE cp.async per group thread.
__device__ __forceinline__ void issue_b_rows(
    __nv_bfloat16* dst, const __nv_bfloat16* __restrict__ Wb,
    int n0, int ck, int wn, int gidx)
{
    int rl  = gidx >> 2;               // local row 0..31
    int seg = gidx & 3;                // 4 segs * 16B = 64B = 32 bf16
    int row = wn * 32 + rl;
    cp16(dst + row * BSTRB + seg * 8,
         Wb + (size_t)(n0 + row) * HID + ck * CHUNK_K + seg * 8);
}

__global__ void __launch_bounds__(512, 1) logits_kernel(
    const float* __restrict__ b_out, float* __restrict__ out)
{
    extern __shared__ char smem_raw[];
    __nv_bfloat16* A_s = (__nv_bfloat16*)smem_raw;                   // [256][ASTR]
    __nv_bfloat16* B_s = (__nv_bfloat16*)(smem_raw + BM * ASTR * 2); // 4*[128][BSTRB]

    const int tid = threadIdx.x;
    const int bid = blockIdx.x;
    const int n0_t0 = bid * BN;                 // tile 0
    const int n0_t1 = (bid + GRID2) * BN;       // tile 1

    const int wid  = tid >> 5;
    const int lane = tid & 31;
    const int wm   = wid >> 2;      // 0..3 -> M offset wm*64
    const int wn   = wid & 3;       // 0..3 -> N offset wn*32 (B row group)
    const int gidx = wm * 32 + lane;           // group-local index 0..127
    const int gr   = lane >> 2;
    const int tig  = lane & 3;
    // A ldmatrix lane mapping (validated):
    const int lm_row = (lane & 15);
    const int lm_col = ((lane >> 4) & 1) << 3;
    // B ldmatrix lane mapping (validated in R5):
    const int bl_row = ((lane >> 4) << 3) + (lane & 7);   // n row within 16
    const int bl_col = ((lane >> 3) & 1) << 3;            // k half (elems)

    // --- group 0: A load ---
    {
        const char* src = (const char*)g_h0;
#pragma unroll
        for (int k = 0; k < 16; k++) {
            int idx = tid + k * 512;       // 8192 segs (256 rows x 32 segs)
            int row = idx >> 5;
            int seg = idx & 31;
            cp16((char*)A_s + row * (ASTR * 2) + seg * 16,
                 src + row * (HID * 2) + seg * 16);
        }
    }
    cp_commit();                                              // group 0: A
    issue_b_rows(B_s + 0 * BBUFB, g_Wbf, n0_t0, 0, wn, gidx); cp_commit();
    issue_b_rows(B_s + 1 * BBUFB, g_Wbf, n0_t0, 1, wn, gidx); cp_commit();
    issue_b_rows(B_s + 2 * BBUFB, g_Wbf, n0_t0, 2, wn, gidx); cp_commit();

    // One-time CTA sync: A + chunk0 complete, A visible to all warps.
    cp_wait2();
    __syncthreads();

    float acc[4][4][4];
#pragma unroll
    for (int mi = 0; mi < 4; mi++)
#pragma unroll
        for (int ni = 0; ni < 4; ni++)
#pragma unroll
            for (int r = 0; r < 4; r++) acc[mi][ni][r] = 0.0f;

#pragma unroll
    for (int g = 0; g < NPHASE; g++) {
        const int c = g & 7;                          // chunk within tile
        cp_wait2();          // own groups: chunk g resident
        group_bar(wn);       // group-wide: chunk-g loads visible

        // ---- issue chunk g+3 (own rows) BEFORE compute (safe: target buf
        //      last read in compute g-1, which every group thread finished
        //      before passing this phase's bar) ----
        if (g + 3 < NPHASE) {
            int gi  = g + 3;
            int nn0 = (gi < NCHUNK) ? n0_t0 : n0_t1;
            issue_b_rows(B_s + (gi & 3) * BBUFB, g_Wbf, nn0, gi & 7, wn, gidx);
        }
        cp_commit();         // unconditional: exact group numbering

        // ---- compute 2 kk steps of chunk g from buf g&3 ----
        const __nv_bfloat16* Bb = B_s + (g & 3) * BBUFB;
#pragma unroll
        for (int kkl = 0; kkl < CHUNK_K / 16; kkl++) {
            const int kbg = c * CHUNK_K + kkl * 16;   // K offset in A
            const int kbl = kkl * 16;                 // K offset in B buf
            uint32_t a[4][4];
#pragma unroll
            for (int mi = 0; mi < 4; mi++) {
                uint32_t addr = (uint32_t)__cvta_generic_to_shared(
                    &A_s[(wm * 64 + mi * 16 + lm_row) * ASTR + kbg + lm_col]);
                asm volatile(
                    "ldmatrix.sync.aligned.m8n8.x4.shared.b16 {%0,%1,%2,%3}, [%4];"
                    : "=r"(a[mi][0]), "=r"(a[mi][1]), "=r"(a[mi][2]), "=r"(a[mi][3])
                    : "r"(addr));
            }
            uint32_t bmat[2][4];  // [h][tile]: h covers n rows wn*32+h*16..+15
#pragma unroll
            for (int h = 0; h < 2; h++) {
                uint32_t addr = (uint32_t)__cvta_generic_to_shared(
                    &Bb[(wn * 32 + h * 16 + bl_row) * BSTRB + kbl + bl_col]);
                asm volatile(
                    "ldmatrix.sync.aligned.m8n8.x4.shared.b16 {%0,%1,%2,%3}, [%4];"
                    : "=r"(bmat[h][0]), "=r"(bmat[h][1]),
                      "=r"(bmat[h][2]), "=r"(bmat[h][3])
                    : "r"(addr));
            }
#pragma unroll
            for (int mi = 0; mi < 4; mi++) {
#pragma unroll
                for (int ni = 0; ni < 4; ni++) {
                    const int h = ni >> 1;
                    const int s = (ni & 1) * 2;
                    asm volatile(
                        "mma.sync.aligned.m16n8k16.row.col.f32.bf16.bf16.f32 "
                        "{%0,%1,%2,%3}, {%4,%5,%6,%7}, {%8,%9}, {%0,%1,%2,%3};"
                        : "+f"(acc[mi][ni][0]), "+f"(acc[mi][ni][1]),
                          "+f"(acc[mi][ni][2]), "+f"(acc[mi][ni][3])
                        : "r"(a[mi][0]), "r"(a[mi][1]), "r"(a[mi][2]), "r"(a[mi][3]),
                          "r"(bmat[h][s]), "r"(bmat[h][s + 1]));
                }
            }
        }

        // ---- tile epilogue after its last chunk (warp-local; no sync) ----
        if (c == NCHUNK - 1) {
            const int n0 = (g < NCHUNK) ? n0_t0 : n0_t1;
            float bo0[4], bo1[4];
#pragma unroll
            for (int ni = 0; ni < 4; ni++) {
                int col = n0 + wn * 32 + ni * 8 + tig * 2;
                bo0[ni] = b_out[col];
                bo1[ni] = b_out[col + 1];
            }
#pragma unroll
            for (int mi = 0; mi < 4; mi++) {
                int row = wm * 64 + mi * 16 + gr;
#pragma unroll
                for (int ni = 0; ni < 4; ni++) {
                    int col = n0 + wn * 32 + ni * 8 + tig * 2;
                    float2 v0 = make_float2(acc[mi][ni][0] + bo0[ni],
                                            acc[mi][ni][1] + bo1[ni]);
                    float2 v1 = make_float2(acc[mi][ni][2] + bo0[ni],
                                            acc[mi][ni][3] + bo1[ni]);
                    *(float2*)(&out[(size_t)row * NCLS + col])       = v0;
                    *(float2*)(&out[(size_t)(row + 8) * NCLS + col]) = v1;
                }
            }
#pragma unroll
            for (int mi = 0; mi < 4; mi++)
#pragma unroll
                for (int ni = 0; ni < 4; ni++)
#pragma unroll
                    for (int r = 0; r < 4; r++) acc[mi][ni][r] = 0.0f;
        }
    }
}

// ---------------------------------------------------------------------------
// Launcher
// Input order: 0=X 1=C_table 2=U_i 3=V_i 4=b_i 5=U_f 6=V_f 7=b_f
//  8=U_c 9=V_c 10=b_c 11=U_o 12=V_o 13=b_o 14..25=layer1 (unused) 26=W_w 27=b_out
// ---------------------------------------------------------------------------
extern "C" void kernel_launch(void* const* d_in, const int* in_sizes, int n_in,
                              void* d_out, int out_size)
{
    const int*   X       = (const int*)d_in[0];
    const float* C_table = (const float*)d_in[1];
    const float* U_i     = (const float*)d_in[2];
    const float* b_i     = (const float*)d_in[4];
    const float* U_c     = (const float*)d_in[8];
    const float* b_c     = (const float*)d_in[10];
    const float* U_o     = (const float*)d_in[11];
    const float* b_o     = (const float*)d_in[13];
    const float* W_w     = (const float*)d_in[26];
    const float* b_out   = (const float*)d_in[27];
    float* out = (float*)d_out;

    prep_kernel<<<384, 256>>>(X, C_table, U_i, b_i, U_c, b_c, U_o, b_o, W_w);

    const int smem_bytes = BM * ASTR * 2 + NBUF * BBUFB * 2;   // 176128
    cudaFuncSetAttribute(logits_kernel,
                         cudaFuncAttributeMaxDynamicSharedMemorySize, smem_bytes);
    logits_kernel<<<GRID2, 512, smem_bytes>>>(b_out, out);
}